// round 12
// baseline (speedup 1.0000x reference)
#include <cuda_runtime.h>
#include <cstdint>

// FastSeqProp: instance-norm(L=200) -> scale/shift -> softmax over C=4
// -> exact JAX threefry categorical (key 42, partitionable) -> straight-through
// -> pad to (N,4,600); outputs [softmax_padded, sampled_padded].
//
// R12 = R10 structure (1 seq/CTA, DMA warp 7) with the CTA-uniform values
// (means, rsqrt(var+eps)) computed REDUNDANTLY per warp after a single
// barrier per pass (same add order, same ops -> bit-identical), removing
// 2 of 4 block barriers and both serialized t<4 sections.
// rel_err must remain exactly 5.770226e-4 (one tolerated argmax flip).

#define LEN   200
#define LPAD  600
#define NCH   4
#define EPSV  1e-5f
#define TINYF 1.17549435e-38f

__device__ __forceinline__ uint32_t rotl32(uint32_t x, int r) {
    return (x << r) | (x >> (32 - r));
}

__device__ __forceinline__ void tf_round(uint32_t& x0, uint32_t& x1, int r) {
    x0 += x1;
    x1 = rotl32(x1, r);
    x1 ^= x0;
}

__device__ __forceinline__ uint32_t tf_bits_k42(uint32_t idx) {
    // threefry2x32, key=(0,42), counter=(0, idx); out = x0 ^ x1 (partitionable)
    const uint32_t ks0 = 0u;
    const uint32_t ks1 = 42u;
    const uint32_t ks2 = 0x1BD11BDAu ^ ks0 ^ ks1;
    uint32_t x0 = 0u + ks0;
    uint32_t x1 = idx + ks1;

    tf_round(x0, x1, 13); tf_round(x0, x1, 15); tf_round(x0, x1, 26); tf_round(x0, x1, 6);
    x0 += ks1; x1 += ks2 + 1u;
    tf_round(x0, x1, 17); tf_round(x0, x1, 29); tf_round(x0, x1, 16); tf_round(x0, x1, 24);
    x0 += ks2; x1 += ks0 + 2u;
    tf_round(x0, x1, 13); tf_round(x0, x1, 15); tf_round(x0, x1, 26); tf_round(x0, x1, 6);
    x0 += ks0; x1 += ks1 + 3u;
    tf_round(x0, x1, 17); tf_round(x0, x1, 29); tf_round(x0, x1, 16); tf_round(x0, x1, 24);
    x0 += ks1; x1 += ks2 + 4u;
    tf_round(x0, x1, 13); tf_round(x0, x1, 15); tf_round(x0, x1, 26); tf_round(x0, x1, 6);
    x0 += ks2; x1 += ks0 + 5u;

    return x0 ^ x1;
}

// w = -log(u), u = uniform in [tiny,1) from bits; exact logf (matches XLA).
__device__ __forceinline__ float expw_from_bits(uint32_t bits) {
    float f = __uint_as_float((bits >> 9) | 0x3f800000u) - 1.0f;
    float u = fmaxf(f, TINYF);
    return 0.0f - logf(u);
}

__device__ __forceinline__ void cp_async16(void* smem_dst, const void* gmem_src) {
    uint32_t s = (uint32_t)__cvta_generic_to_shared(smem_dst);
    asm volatile("cp.async.cg.shared.global [%0], [%1], 16;" :: "r"(s), "l"(gmem_src));
}

__global__ __launch_bounds__(256) void fastseqprop_kernel(
    const float* __restrict__ ts,    // (N,4,200)
    const float* __restrict__ scw,   // (N,4,1)
    const float* __restrict__ shw,   // (N,4,1)
    const float* __restrict__ up,    // (N,4,200)
    const float* __restrict__ dn,    // (N,4,200)
    float* __restrict__ out,         // (2,N,4,600) flattened
    uint32_t half_out)               // N*4*600
{
    const uint32_t n    = blockIdx.x;
    const uint32_t t    = threadIdx.x;
    const uint32_t lane = t & 31u;
    const uint32_t wid  = t >> 5;

    __shared__ float  red[7][4];
    __shared__ float  sw[NCH * LEN];     // w = -log(u), layout [c*200 + l]
    __shared__ float4 spad[400];         // [0:200)=up f4, [200:400)=dn f4

    const uint32_t base = n * (NCH * LEN);   // == flat gumbel base (N,L,4)

    // ================= warp 7: DMA warp + 4th threefry draw =================
    if (wid == 7u) {
        const float4* up4 = (const float4*)up + n * 200u;
        const float4* dn4 = (const float4*)dn + n * 200u;
        #pragma unroll
        for (uint32_t i = 0; i < 13u; i++) {
            const uint32_t idx = i * 32u + lane;
            if (idx < 400u) {
                const float4* src = (idx < 200u) ? (up4 + idx) : (dn4 + (idx - 200u));
                cp_async16(&spad[idx], src);
            }
        }
        asm volatile("cp.async.commit_group;" ::: "memory");

        // 4 threefry draws: j = t, t+256, t+512, t+544
        {
            const uint32_t j0 = t;
            const uint32_t j1 = t + 256u;
            const uint32_t j2 = t + 512u;
            const uint32_t j3 = t + 544u;
            const uint32_t b0 = tf_bits_k42(base + j0);
            const uint32_t b1 = tf_bits_k42(base + j1);
            const uint32_t b2 = tf_bits_k42(base + j2);
            const uint32_t b3 = tf_bits_k42(base + j3);
            sw[(j0 & 3u) * LEN + (j0 >> 2)] = expw_from_bits(b0);
            sw[(j1 & 3u) * LEN + (j1 >> 2)] = expw_from_bits(b1);
            sw[(j2 & 3u) * LEN + (j2 >> 2)] = expw_from_bits(b2);
            sw[(j3 & 3u) * LEN + (j3 >> 2)] = expw_from_bits(b3);
        }
        // publish sw writes (warps 0-6 bar.sync 1 before the argmin phase)
        asm volatile("bar.arrive 1, 256;" ::: "memory");

        // drain pad prefetch; lanes read only their own cp.async'd slots
        asm volatile("cp.async.wait_group 0;" ::: "memory");

        float4* o0 = (float4*)out + n * 600u;
        float4* o1 = o0 + (half_out >> 2);
        #pragma unroll 1
        for (uint32_t i = 0; i < 13u; i++) {
            const uint32_t idx = i * 32u + lane;
            if (idx < 400u) {
                const float4 v = spad[idx];
                uint32_t off;
                if (idx < 200u) {
                    const uint32_t ch = idx / 50u;
                    off = ch * 150u + (idx - ch * 50u);
                } else {
                    const uint32_t j  = idx - 200u;
                    const uint32_t ch = j / 50u;
                    off = ch * 150u + 100u + (j - ch * 50u);
                }
                o0[off] = v;
                o1[off] = v;
            }
        }
        return;
    }

    // ================= warps 0-6: norm + softmax + sample =================
    const bool act = (t < LEN);
    const uint32_t wbase = n * NCH;
    const uint32_t cl = lane & 3u;   // channel this lane computes redundantly

    // preload ts + weights (latency hidden under threefry)
    float x0 = 0.f, x1 = 0.f, x2 = 0.f, x3 = 0.f;
    float scv[4], shv[4];
    if (act) {
        x0 = ts[base + 0 * LEN + t];
        x1 = ts[base + 1 * LEN + t];
        x2 = ts[base + 2 * LEN + t];
        x3 = ts[base + 3 * LEN + t];
        #pragma unroll
        for (int c = 0; c < 4; c++) {
            scv[c] = scw[wbase + (uint32_t)c];
            shv[c] = shw[wbase + (uint32_t)c];
        }
    }

    // dense threefry: 3 draws per thread (j = t, t+256, t+512)
    {
        const uint32_t j0 = t;
        const uint32_t j1 = t + 256u;
        const uint32_t j2 = t + 512u;
        const uint32_t b0 = tf_bits_k42(base + j0);
        const uint32_t b1 = tf_bits_k42(base + j1);
        const uint32_t b2 = tf_bits_k42(base + j2);
        sw[(j0 & 3u) * LEN + (j0 >> 2)] = expw_from_bits(b0);
        sw[(j1 & 3u) * LEN + (j1 >> 2)] = expw_from_bits(b1);
        sw[(j2 & 3u) * LEN + (j2 >> 2)] = expw_from_bits(b2);
    }

    // ---- pass 1: sums -> means (redundant per-warp finish, ONE barrier) ----
    {
        float v0 = x0, v1 = x1, v2 = x2, v3 = x3;
        #pragma unroll
        for (int o = 16; o > 0; o >>= 1) {
            v0 += __shfl_down_sync(0xffffffffu, v0, o);
            v1 += __shfl_down_sync(0xffffffffu, v1, o);
            v2 += __shfl_down_sync(0xffffffffu, v2, o);
            v3 += __shfl_down_sync(0xffffffffu, v3, o);
        }
        if (lane == 0) { red[wid][0] = v0; red[wid][1] = v1; red[wid][2] = v2; red[wid][3] = v3; }
    }
    asm volatile("bar.sync 2, 224;" ::: "memory");
    float bcm0, bcm1, bcm2, bcm3;
    {
        // every lane: sum channel (lane&3) in the SAME w-ascending order
        float s = red[0][cl];
        #pragma unroll
        for (int w = 1; w < 7; w++) s += red[w][cl];
        const float m = s / 200.0f;            // same op as validated kernels
        bcm0 = __shfl_sync(0xffffffffu, m, 0);
        bcm1 = __shfl_sync(0xffffffffu, m, 1);
        bcm2 = __shfl_sync(0xffffffffu, m, 2);
        bcm3 = __shfl_sync(0xffffffffu, m, 3);
    }

    const float d0 = act ? (x0 - bcm0) : 0.f;
    const float d1 = act ? (x1 - bcm1) : 0.f;
    const float d2 = act ? (x2 - bcm2) : 0.f;
    const float d3 = act ? (x3 - bcm3) : 0.f;

    // ---- pass 2: centered sum of squares -> rsqrt(var+eps), ONE barrier ----
    {
        float v0 = d0 * d0, v1 = d1 * d1, v2 = d2 * d2, v3 = d3 * d3;
        #pragma unroll
        for (int o = 16; o > 0; o >>= 1) {
            v0 += __shfl_down_sync(0xffffffffu, v0, o);
            v1 += __shfl_down_sync(0xffffffffu, v1, o);
            v2 += __shfl_down_sync(0xffffffffu, v2, o);
            v3 += __shfl_down_sync(0xffffffffu, v3, o);
        }
        if (lane == 0) { red[wid][0] = v0; red[wid][1] = v1; red[wid][2] = v2; red[wid][3] = v3; }
    }
    // pairs with warp 7's bar.arrive: orders red writes AND all sw writes
    asm volatile("bar.sync 1, 256;" ::: "memory");
    float bcr0, bcr1, bcr2, bcr3;
    {
        float s = red[0][cl];
        #pragma unroll
        for (int w = 1; w < 7; w++) s += red[w][cl];
        const float r = rsqrtf(s / 200.0f + EPSV);
        bcr0 = __shfl_sync(0xffffffffu, r, 0);
        bcr1 = __shfl_sync(0xffffffffu, r, 1);
        bcr2 = __shfl_sync(0xffffffffu, r, 2);
        bcr3 = __shfl_sync(0xffffffffu, r, 3);
    }

    // ---- element phase (t < 200): softmax + race argmin + mid stores ----
    if (act) {
        float sc[4];
        sc[0] = (d0 * bcr0) * scv[0] + shv[0];
        sc[1] = (d1 * bcr1) * scv[1] + shv[1];
        sc[2] = (d2 * bcr2) * scv[2] + shv[2];
        sc[3] = (d3 * bcr3) * scv[3] + shv[3];

        const float mx = fmaxf(fmaxf(sc[0], sc[1]), fmaxf(sc[2], sc[3]));
        float ex[4];
        #pragma unroll
        for (int c = 0; c < 4; c++) ex[c] = expf(sc[c] - mx);
        const float ssum = ((ex[0] + ex[1]) + ex[2]) + ex[3];
        float soft[4];
        #pragma unroll
        for (int c = 0; c < 4; c++) soft[c] = __fdividef(ex[c], ssum);

        // exponential-races argmin: argmin_c w_c / ex_c (cross-multiplied)
        float wb = sw[t];
        float eb = ex[0];
        int   bi = 0;
        #pragma unroll
        for (int c = 1; c < 4; c++) {
            const float wc = sw[(uint32_t)c * LEN + t];
            if (wc * eb < wb * ex[c]) { wb = wc; eb = ex[c]; bi = c; }
        }

        float* out0 = out;
        float* out1 = out + half_out;
        const uint32_t obase = n * (NCH * LPAD);
        #pragma unroll
        for (int c = 0; c < 4; c++) {
            const float s_v = soft[c];
            const float oh  = (c == bi) ? 1.0f : 0.0f;
            const float samp = (oh - s_v) + s_v;   // straight-through
            const uint32_t mid = obase + (uint32_t)c * LPAD + LEN + t;
            out0[mid] = s_v;
            out1[mid] = samp;
        }
    }
}

extern "C" void kernel_launch(void* const* d_in, const int* in_sizes, int n_in,
                              void* d_out, int out_size) {
    const float* ts  = (const float*)d_in[0];
    const float* scw = (const float*)d_in[1];
    const float* shw = (const float*)d_in[2];
    const float* up  = (const float*)d_in[3];
    const float* dn  = (const float*)d_in[4];
    float* out = (float*)d_out;

    const int nseq = in_sizes[0] / (NCH * LEN);          // 8192
    const uint32_t half_out = (uint32_t)(out_size / 2);  // N*4*600

    fastseqprop_kernel<<<nseq, 256>>>(ts, scw, shw, up, dn, out, half_out);
}

// round 13
// speedup vs baseline: 1.1309x; 1.1309x over previous
#include <cuda_runtime.h>
#include <cstdint>

// FastSeqProp: instance-norm(L=200) -> scale/shift -> softmax over C=4
// -> exact JAX threefry categorical (key 42, partitionable) -> straight-through
// -> pad to (N,4,600); outputs [softmax_padded, sampled_padded].
//
// R13 = R10 chassis (best: ncu 45.6) + safe instruction trims:
//  - sw slot strength reduction (slot0 + 64k)
//  - warp-7 pad loops restructured channel-wise (no /50 divisions)
//  - single-reciprocal softmax (argmin uses ex directly; soft is tolerance-bound)
// All argmin-relevant float math bit-identical to the validated 1-flip kernel.

#define LEN   200
#define LPAD  600
#define NCH   4
#define EPSV  1e-5f
#define TINYF 1.17549435e-38f

__device__ __forceinline__ uint32_t rotl32(uint32_t x, int r) {
    return (x << r) | (x >> (32 - r));
}

__device__ __forceinline__ void tf_round(uint32_t& x0, uint32_t& x1, int r) {
    x0 += x1;
    x1 = rotl32(x1, r);
    x1 ^= x0;
}

__device__ __forceinline__ uint32_t tf_bits_k42(uint32_t idx) {
    // threefry2x32, key=(0,42), counter=(0, idx); out = x0 ^ x1 (partitionable)
    const uint32_t ks0 = 0u;
    const uint32_t ks1 = 42u;
    const uint32_t ks2 = 0x1BD11BDAu ^ ks0 ^ ks1;
    uint32_t x0 = 0u + ks0;
    uint32_t x1 = idx + ks1;

    tf_round(x0, x1, 13); tf_round(x0, x1, 15); tf_round(x0, x1, 26); tf_round(x0, x1, 6);
    x0 += ks1; x1 += ks2 + 1u;
    tf_round(x0, x1, 17); tf_round(x0, x1, 29); tf_round(x0, x1, 16); tf_round(x0, x1, 24);
    x0 += ks2; x1 += ks0 + 2u;
    tf_round(x0, x1, 13); tf_round(x0, x1, 15); tf_round(x0, x1, 26); tf_round(x0, x1, 6);
    x0 += ks0; x1 += ks1 + 3u;
    tf_round(x0, x1, 17); tf_round(x0, x1, 29); tf_round(x0, x1, 16); tf_round(x0, x1, 24);
    x0 += ks1; x1 += ks2 + 4u;
    tf_round(x0, x1, 13); tf_round(x0, x1, 15); tf_round(x0, x1, 26); tf_round(x0, x1, 6);
    x0 += ks2; x1 += ks0 + 5u;

    return x0 ^ x1;
}

// w = -log(u), u = uniform in [tiny,1) from bits; exact logf (matches XLA).
__device__ __forceinline__ float expw_from_bits(uint32_t bits) {
    float f = __uint_as_float((bits >> 9) | 0x3f800000u) - 1.0f;
    float u = fmaxf(f, TINYF);
    return 0.0f - logf(u);
}

__device__ __forceinline__ void cp_async16(void* smem_dst, const void* gmem_src) {
    uint32_t s = (uint32_t)__cvta_generic_to_shared(smem_dst);
    asm volatile("cp.async.cg.shared.global [%0], [%1], 16;" :: "r"(s), "l"(gmem_src));
}

__global__ __launch_bounds__(256) void fastseqprop_kernel(
    const float* __restrict__ ts,    // (N,4,200)
    const float* __restrict__ scw,   // (N,4,1)
    const float* __restrict__ shw,   // (N,4,1)
    const float* __restrict__ up,    // (N,4,200)
    const float* __restrict__ dn,    // (N,4,200)
    float* __restrict__ out,         // (2,N,4,600) flattened
    uint32_t half_out)               // N*4*600
{
    const uint32_t n    = blockIdx.x;
    const uint32_t t    = threadIdx.x;
    const uint32_t lane = t & 31u;
    const uint32_t wid  = t >> 5;

    __shared__ float  red[7][4];
    __shared__ float  bcm[4];            // means
    __shared__ float  bcr[4];            // rsqrt(var+eps)
    __shared__ float  sw[NCH * LEN];     // w = -log(u), layout [c*200 + l]
    __shared__ float4 spad[400];         // [ch*50+q]=up, [200+ch*50+q]=dn

    const uint32_t base  = n * (NCH * LEN);   // == flat gumbel base (N,L,4)
    const uint32_t slot0 = (t & 3u) * LEN + (t >> 2);

    // ================= warp 7: DMA warp + 4th threefry draw =================
    if (wid == 7u) {
        const float4* up4 = (const float4*)up + n * 200u;
        const float4* dn4 = (const float4*)dn + n * 200u;
        #pragma unroll
        for (uint32_t ch = 0; ch < 4u; ch++) {
            const uint32_t b = ch * 50u + lane;
            cp_async16(&spad[b], &up4[b]);
            cp_async16(&spad[200u + b], &dn4[b]);
            if (lane < 18u) {
                cp_async16(&spad[b + 32u], &up4[b + 32u]);
                cp_async16(&spad[200u + b + 32u], &dn4[b + 32u]);
            }
        }
        asm volatile("cp.async.commit_group;" ::: "memory");

        // 4 threefry draws: j = t, t+256, t+512, t+544 (slots +0,+64,+128,+136)
        sw[slot0]        = expw_from_bits(tf_bits_k42(base + t));
        sw[slot0 + 64u]  = expw_from_bits(tf_bits_k42(base + t + 256u));
        sw[slot0 + 128u] = expw_from_bits(tf_bits_k42(base + t + 512u));
        sw[slot0 + 136u] = expw_from_bits(tf_bits_k42(base + t + 544u));
        // publish sw writes (warps 0-6 bar.sync 1 before the argmin phase)
        asm volatile("bar.arrive 1, 256;" ::: "memory");

        // drain pad prefetch; lanes read only their own cp.async'd slots
        asm volatile("cp.async.wait_group 0;" ::: "memory");

        float4* o0 = (float4*)out + n * 600u;
        float4* o1 = o0 + (half_out >> 2);
        #pragma unroll
        for (uint32_t ch = 0; ch < 4u; ch++) {
            const uint32_t sb = ch * 50u + lane;    // smem index (up)
            const uint32_t ob = ch * 150u + lane;   // gmem f4 offset (up)
            {
                const float4 v = spad[sb];
                o0[ob] = v; o1[ob] = v;
            }
            {
                const float4 v = spad[200u + sb];
                o0[ob + 100u] = v; o1[ob + 100u] = v;
            }
            if (lane < 18u) {
                const float4 v = spad[sb + 32u];
                o0[ob + 32u] = v; o1[ob + 32u] = v;
                const float4 w2 = spad[200u + sb + 32u];
                o0[ob + 132u] = w2; o1[ob + 132u] = w2;
            }
        }
        return;
    }

    // ================= warps 0-6: norm + softmax + sample =================
    const bool act = (t < LEN);
    const uint32_t wbase = n * NCH;

    // preload ts + weights (latency hidden under threefry)
    float x0 = 0.f, x1 = 0.f, x2 = 0.f, x3 = 0.f;
    float scv[4], shv[4];
    if (act) {
        x0 = ts[base + 0 * LEN + t];
        x1 = ts[base + 1 * LEN + t];
        x2 = ts[base + 2 * LEN + t];
        x3 = ts[base + 3 * LEN + t];
        #pragma unroll
        for (int c = 0; c < 4; c++) {
            scv[c] = scw[wbase + (uint32_t)c];
            shv[c] = shw[wbase + (uint32_t)c];
        }
    }

    // dense threefry: 3 draws per thread (slots slot0, +64, +128)
    sw[slot0]        = expw_from_bits(tf_bits_k42(base + t));
    sw[slot0 + 64u]  = expw_from_bits(tf_bits_k42(base + t + 256u));
    sw[slot0 + 128u] = expw_from_bits(tf_bits_k42(base + t + 512u));

    // ---- pass 1: sums -> means ----
    {
        float v0 = x0, v1 = x1, v2 = x2, v3 = x3;
        #pragma unroll
        for (int o = 16; o > 0; o >>= 1) {
            v0 += __shfl_down_sync(0xffffffffu, v0, o);
            v1 += __shfl_down_sync(0xffffffffu, v1, o);
            v2 += __shfl_down_sync(0xffffffffu, v2, o);
            v3 += __shfl_down_sync(0xffffffffu, v3, o);
        }
        if (lane == 0) { red[wid][0] = v0; red[wid][1] = v1; red[wid][2] = v2; red[wid][3] = v3; }
    }
    asm volatile("bar.sync 2, 224;" ::: "memory");
    if (t < 4u) {
        float s = red[0][t];
        #pragma unroll
        for (int w = 1; w < 7; w++) s += red[w][t];
        bcm[t] = s / 200.0f;
    }
    asm volatile("bar.sync 2, 224;" ::: "memory");

    const float d0 = act ? (x0 - bcm[0]) : 0.f;
    const float d1 = act ? (x1 - bcm[1]) : 0.f;
    const float d2 = act ? (x2 - bcm[2]) : 0.f;
    const float d3 = act ? (x3 - bcm[3]) : 0.f;

    // ---- pass 2: centered sum of squares -> rsqrt(var+eps) ----
    {
        float v0 = d0 * d0, v1 = d1 * d1, v2 = d2 * d2, v3 = d3 * d3;
        #pragma unroll
        for (int o = 16; o > 0; o >>= 1) {
            v0 += __shfl_down_sync(0xffffffffu, v0, o);
            v1 += __shfl_down_sync(0xffffffffu, v1, o);
            v2 += __shfl_down_sync(0xffffffffu, v2, o);
            v3 += __shfl_down_sync(0xffffffffu, v3, o);
        }
        if (lane == 0) { red[wid][0] = v0; red[wid][1] = v1; red[wid][2] = v2; red[wid][3] = v3; }
    }
    // pairs with warp 7's bar.arrive: orders red writes AND warp7's sw writes
    asm volatile("bar.sync 1, 256;" ::: "memory");
    if (t < 4u) {
        float s = red[0][t];
        #pragma unroll
        for (int w = 1; w < 7; w++) s += red[w][t];
        bcr[t] = rsqrtf(s / 200.0f + EPSV);
    }
    asm volatile("bar.sync 2, 224;" ::: "memory");

    // ---- element phase (t < 200): softmax + race argmin + mid stores ----
    if (act) {
        float sc[4];
        sc[0] = (d0 * bcr[0]) * scv[0] + shv[0];
        sc[1] = (d1 * bcr[1]) * scv[1] + shv[1];
        sc[2] = (d2 * bcr[2]) * scv[2] + shv[2];
        sc[3] = (d3 * bcr[3]) * scv[3] + shv[3];

        const float mx = fmaxf(fmaxf(sc[0], sc[1]), fmaxf(sc[2], sc[3]));
        float ex[4];
        #pragma unroll
        for (int c = 0; c < 4; c++) ex[c] = expf(sc[c] - mx);
        const float ssum = ((ex[0] + ex[1]) + ex[2]) + ex[3];
        const float rs = __fdividef(1.0f, ssum);   // soft only feeds outputs
                                                   // (argmin uses ex directly)

        // exponential-races argmin: argmin_c w_c / ex_c (cross-multiplied)
        float wb = sw[t];
        float eb = ex[0];
        int   bi = 0;
        #pragma unroll
        for (int c = 1; c < 4; c++) {
            const float wc = sw[(uint32_t)c * LEN + t];
            if (wc * eb < wb * ex[c]) { wb = wc; eb = ex[c]; bi = c; }
        }

        float* out0 = out;
        float* out1 = out + half_out;
        const uint32_t obase = n * (NCH * LPAD);
        #pragma unroll
        for (int c = 0; c < 4; c++) {
            const float s_v = ex[c] * rs;
            const float oh  = (c == bi) ? 1.0f : 0.0f;
            const float samp = (oh - s_v) + s_v;   // straight-through
            const uint32_t mid = obase + (uint32_t)c * LPAD + LEN + t;
            out0[mid] = s_v;
            out1[mid] = samp;
        }
    }
}

extern "C" void kernel_launch(void* const* d_in, const int* in_sizes, int n_in,
                              void* d_out, int out_size) {
    const float* ts  = (const float*)d_in[0];
    const float* scw = (const float*)d_in[1];
    const float* shw = (const float*)d_in[2];
    const float* up  = (const float*)d_in[3];
    const float* dn  = (const float*)d_in[4];
    float* out = (float*)d_out;

    const int nseq = in_sizes[0] / (NCH * LEN);          // 8192
    const uint32_t half_out = (uint32_t)(out_size / 2);  // N*4*600

    fastseqprop_kernel<<<nseq, 256>>>(ts, scw, shw, up, dn, out, half_out);
}